// round 8
// baseline (speedup 1.0000x reference)
#include <cuda_runtime.h>
#include <cstdint>

// Problem constants (fixed by setup_inputs)
#define B_      16
#define T_      1024
#define D_      384
#define MAXDUR_ 4
#define OUTLEN_ (T_ * MAXDUR_)      // 4096
#define D4_     (D_ / 4)            // 96 float4 per row

#define G_THREADS    384            // gather CTA size
#define ROWS_PER_CTA 16             // 16 rows * 96 f4 = 1536 = 384 * 4
#define RPT          4              // rows per thread

// Scratch: per-output-frame source index, -1 => pad (zero fill)
__device__ int g_idx[B_ * OUTLEN_];

// ---------------------------------------------------------------------------
// Kernel 1: warp-shuffle inclusive scan of durations + scatter-expand of the
// index table. 16 blocks (one per batch row), 1024 threads.
// ---------------------------------------------------------------------------
__global__ void __launch_bounds__(T_) scan_idx_kernel(const int* __restrict__ ds) {
    __shared__ int wsum[32];
    const int b    = blockIdx.x;
    const int tid  = threadIdx.x;
    const int lane = tid & 31;
    const int warp = tid >> 5;

    const int d = ds[b * T_ + tid];

    // warp-level inclusive scan
    int x = d;
    #pragma unroll
    for (int off = 1; off < 32; off <<= 1) {
        int y = __shfl_up_sync(0xffffffffu, x, off);
        if (lane >= off) x += y;
    }
    if (lane == 31) wsum[warp] = x;
    __syncthreads();

    if (warp == 0) {
        int w = wsum[lane];
        #pragma unroll
        for (int off = 1; off < 32; off <<= 1) {
            int y = __shfl_up_sync(0xffffffffu, w, off);
            if (lane >= off) w += y;
        }
        wsum[lane] = w;
    }
    __syncthreads();

    const int base  = (warp > 0) ? wsum[warp - 1] : 0;
    const int end   = base + x;          // inclusive cumsum for token tid
    const int start = end - d;
    const int total = wsum[31];

    int* __restrict__ gi = &g_idx[b * OUTLEN_];

    // scatter-expand: token tid covers output frames [start, end)
    for (int t = start; t < end; t++) gi[t] = tid;

    // pad tail
    for (int t = total + tid; t < OUTLEN_; t += T_) gi[t] = -1;
}

// ---------------------------------------------------------------------------
// Kernel 2: streaming gather, L2-residency-aware.
//   xs / g_idx reads: __ldcs (evict-first) -> transient, don't displace out.
//   out stores: default st.global (evict-normal) -> out owns the L2, so the
//   per-replay DRAM write drain collapses in steady state.
// One CTA = 16 output rows, 4 rows/thread (proven best geometry, regs=32).
// ---------------------------------------------------------------------------
__global__ void __launch_bounds__(G_THREADS) gather_kernel(
    const float4* __restrict__ xs, float4* __restrict__ out) {
    const int lr   = threadIdx.x / D4_;        // 0..3 local row within slice
    const int c    = threadIdx.x - lr * D4_;   // 0..95 column
    const int row0 = blockIdx.x * ROWS_PER_CTA;
    const int b    = row0 >> 12;               // same batch for whole CTA
    const float4* __restrict__ xb = xs + (size_t)b * T_ * D4_;

    // batch the 4 independent idx loads (evict-first: tiny, transient)
    int idxs[RPT];
    #pragma unroll
    for (int k = 0; k < RPT; k++)
        idxs[k] = __ldcs(&g_idx[row0 + k * 4 + lr]);

    // batch the 4 independent gathers (evict-first: keep xs out of L2's way)
    float4 v[RPT];
    #pragma unroll
    for (int k = 0; k < RPT; k++) {
        if (idxs[k] >= 0)
            v[k] = __ldcs(&xb[(size_t)idxs[k] * D4_ + c]);
        else
            v[k] = make_float4(0.f, 0.f, 0.f, 0.f);
    }

    // evict-normal stores: out wins L2 residency across graph replays
    #pragma unroll
    for (int k = 0; k < RPT; k++)
        out[(size_t)(row0 + k * 4 + lr) * D4_ + c] = v[k];
}

extern "C" void kernel_launch(void* const* d_in, const int* in_sizes, int n_in,
                              void* d_out, int out_size) {
    const float* xs = (const float*)d_in[0];   // (16,1024,384) f32
    const int*   ds = (const int*)d_in[1];     // (16,1024) i32
    float* out = (float*)d_out;                // (16,4096,384) f32

    scan_idx_kernel<<<B_, T_>>>(ds);
    gather_kernel<<<(B_ * OUTLEN_) / ROWS_PER_CTA, G_THREADS>>>(
        (const float4*)xs, (float4*)out);
}

// round 9
// speedup vs baseline: 1.2838x; 1.2838x over previous
#include <cuda_runtime.h>
#include <cstdint>

// Problem constants (fixed by setup_inputs)
#define B_      16
#define T_      1024
#define D_      384
#define MAXDUR_ 4
#define OUTLEN_ (T_ * MAXDUR_)      // 4096
#define D4_     (D_ / 4)            // 96 float4 per row

#define G_THREADS    384            // gather CTA size
#define ROWS_PER_CTA 16             // 16 rows * 96 f4 = 1536 = 384 * 4
#define RPT          4              // rows per thread

// Scratch: per-output-frame source index, -1 => pad (zero fill)
__device__ int g_idx[B_ * OUTLEN_];

// ---------------------------------------------------------------------------
// Kernel 1: warp-shuffle inclusive scan of durations + scatter-expand of the
// index table. 16 blocks (one per batch row), 1024 threads.
// ---------------------------------------------------------------------------
__global__ void __launch_bounds__(T_) scan_idx_kernel(const int* __restrict__ ds) {
    __shared__ int wsum[32];
    const int b    = blockIdx.x;
    const int tid  = threadIdx.x;
    const int lane = tid & 31;
    const int warp = tid >> 5;

    const int d = ds[b * T_ + tid];

    // warp-level inclusive scan
    int x = d;
    #pragma unroll
    for (int off = 1; off < 32; off <<= 1) {
        int y = __shfl_up_sync(0xffffffffu, x, off);
        if (lane >= off) x += y;
    }
    if (lane == 31) wsum[warp] = x;
    __syncthreads();

    if (warp == 0) {
        int w = wsum[lane];
        #pragma unroll
        for (int off = 1; off < 32; off <<= 1) {
            int y = __shfl_up_sync(0xffffffffu, w, off);
            if (lane >= off) w += y;
        }
        wsum[lane] = w;
    }
    __syncthreads();

    const int base  = (warp > 0) ? wsum[warp - 1] : 0;
    const int end   = base + x;          // inclusive cumsum for token tid
    const int start = end - d;
    const int total = wsum[31];

    int* __restrict__ gi = &g_idx[b * OUTLEN_];

    // scatter-expand: token tid covers output frames [start, end)
    for (int t = start; t < end; t++) gi[t] = tid;

    // pad tail
    for (int t = total + tid; t < OUTLEN_; t += T_) gi[t] = -1;
}

// ---------------------------------------------------------------------------
// Kernel 2: streaming gather (R2-proven config: __ldg reads, __stcs stores).
// PDL: all setup/address math runs overlapped with the scan kernel; we block
// on grid dependencies only right before the first dependent load.
// ---------------------------------------------------------------------------
__global__ void __launch_bounds__(G_THREADS) gather_kernel(
    const float4* __restrict__ xs, float4* __restrict__ out) {
    const int lr   = threadIdx.x / D4_;        // 0..3 local row within slice
    const int c    = threadIdx.x - lr * D4_;   // 0..95 column
    const int row0 = blockIdx.x * ROWS_PER_CTA;
    const int b    = row0 >> 12;               // same batch for whole CTA
    const float4* __restrict__ xb = xs + (size_t)b * T_ * D4_;

#if __CUDA_ARCH__ >= 900
    cudaGridDependencySynchronize();           // wait for scan_idx_kernel
#endif

    // batch the 4 independent idx loads
    int idxs[RPT];
    #pragma unroll
    for (int k = 0; k < RPT; k++)
        idxs[k] = g_idx[row0 + k * 4 + lr];

    // batch the 4 independent gathers
    float4 v[RPT];
    #pragma unroll
    for (int k = 0; k < RPT; k++) {
        if (idxs[k] >= 0)
            v[k] = __ldg(&xb[(size_t)idxs[k] * D4_ + c]);
        else
            v[k] = make_float4(0.f, 0.f, 0.f, 0.f);
    }

    // streaming stores: don't let 100MB of dirty lines squat in L2 —
    // proven 6us faster in steady-state graph replay than evict-normal.
    #pragma unroll
    for (int k = 0; k < RPT; k++)
        __stcs(&out[(size_t)(row0 + k * 4 + lr) * D4_ + c], v[k]);
}

extern "C" void kernel_launch(void* const* d_in, const int* in_sizes, int n_in,
                              void* d_out, int out_size) {
    const float* xs = (const float*)d_in[0];   // (16,1024,384) f32
    const int*   ds = (const int*)d_in[1];     // (16,1024) i32
    float* out = (float*)d_out;                // (16,4096,384) f32

    scan_idx_kernel<<<B_, T_>>>(ds);

    // PDL launch: overlap gather's CTA rollout/prologue with the scan.
    cudaLaunchConfig_t cfg = {};
    cfg.gridDim  = dim3((B_ * OUTLEN_) / ROWS_PER_CTA);
    cfg.blockDim = dim3(G_THREADS);
    cudaLaunchAttribute attrs[1];
    attrs[0].id = cudaLaunchAttributeProgrammaticStreamSerialization;
    attrs[0].val.programmaticStreamSerializationAllowed = 1;
    cfg.attrs = attrs;
    cfg.numAttrs = 1;
    cudaLaunchKernelEx(&cfg, gather_kernel, (const float4*)xs, (float4*)out);
}